// round 1
// baseline (speedup 1.0000x reference)
#include <cuda_runtime.h>

#define Bb 2
#define Tt 4096
#define Cc 768
#define Hh 12
#define Dd 64

// Scratch (device globals: allocation-free per harness rules)
__device__ float g_qkv[(size_t)Bb * Tt * 3 * Cc];   // (B*T, 3C) row-major: [Q | K | V]
__device__ float g_y[(size_t)Bb * Tt * Cc];         // (B*T, C) attention output

// ---------------------------------------------------------------------------
// Tiled SGEMM: C[M,N] = A[M,K] @ B[K,N].  BM=BN=128, BK=8, 8x8 per thread,
// 256 threads. All dims here are multiples of the tile sizes (no bounds checks).
// ---------------------------------------------------------------------------
__global__ __launch_bounds__(256) void sgemm128(const float* __restrict__ A,
                                                const float* __restrict__ B,
                                                float* __restrict__ C,
                                                int M, int N, int K) {
    const int BM = 128, BN = 128, BK = 8, TM = 8, TN = 8;
    __shared__ float As[BK][BM];   // transposed A tile
    __shared__ float Bs[BK][BN];

    int tid  = threadIdx.x;
    int crow = blockIdx.y * BM;
    int ccol = blockIdx.x * BN;

    int tR = tid / 16;             // 0..15
    int tC = tid % 16;             // 0..15

    int aRow = tid / 2;            // 0..127
    int aCol = (tid % 2) * 4;      // 0 or 4
    int bRow = tid / 32;           // 0..7
    int bCol = (tid % 32) * 4;     // 0..124

    const float* Ap = A + (size_t)(crow + aRow) * K + aCol;
    const float* Bp = B + (size_t)bRow * N + ccol + bCol;

    float accv[TM][TN];
#pragma unroll
    for (int i = 0; i < TM; i++)
#pragma unroll
        for (int j = 0; j < TN; j++) accv[i][j] = 0.f;

    for (int k0 = 0; k0 < K; k0 += BK) {
        float4 a4 = *(const float4*)(Ap + k0);
        As[aCol + 0][aRow] = a4.x;
        As[aCol + 1][aRow] = a4.y;
        As[aCol + 2][aRow] = a4.z;
        As[aCol + 3][aRow] = a4.w;
        *(float4*)&Bs[bRow][bCol] = *(const float4*)(Bp + (size_t)k0 * N);
        __syncthreads();

#pragma unroll
        for (int k = 0; k < BK; k++) {
            float ra[TM], rb[TN];
#pragma unroll
            for (int i = 0; i < TM; i++) ra[i] = As[k][tR * TM + i];
#pragma unroll
            for (int j = 0; j < TN; j++) rb[j] = Bs[k][tC * TN + j];
#pragma unroll
            for (int i = 0; i < TM; i++)
#pragma unroll
                for (int j = 0; j < TN; j++)
                    accv[i][j] = fmaf(ra[i], rb[j], accv[i][j]);
        }
        __syncthreads();
    }

#pragma unroll
    for (int i = 0; i < TM; i++) {
        float* cp = C + (size_t)(crow + tR * TM + i) * N + ccol + tC * TN;
        *(float4*)cp       = make_float4(accv[i][0], accv[i][1], accv[i][2], accv[i][3]);
        *(float4*)(cp + 4) = make_float4(accv[i][4], accv[i][5], accv[i][6], accv[i][7]);
    }
}

// ---------------------------------------------------------------------------
// Causal flash attention, fp32 SIMT. One query row per thread, 128 rows/CTA.
// grid = (T/128, B*H). K/V streamed in 64-key tiles through shared memory.
// q pre-scaled by (1/sqrt(D)) * log2(e) so softmax uses exp2f (MUFU.EX2).
// Online softmax in 16-key chunks (s[] stays in registers).
// ---------------------------------------------------------------------------
__global__ __launch_bounds__(128) void attn_kernel(const float* __restrict__ qkv,
                                                   float* __restrict__ y) {
    __shared__ float Ks[64][64];
    __shared__ float Vs[64][64];

    const int bh = blockIdx.y;
    const int b  = bh / Hh;
    const int h  = bh % Hh;
    const int t  = blockIdx.x * 128 + threadIdx.x;   // this thread's query row
    const size_t rs = 3 * Cc;                        // qkv row stride

    const float* qp = qkv + ((size_t)(b * Tt + t)) * rs + h * Dd;
    const float sc = 0.125f * 1.44269504088896340736f;  // 1/sqrt(64) * log2(e)

    float q[Dd];
#pragma unroll
    for (int d = 0; d < Dd; d += 4) {
        float4 v = *(const float4*)(qp + d);
        q[d] = v.x * sc; q[d + 1] = v.y * sc; q[d + 2] = v.z * sc; q[d + 3] = v.w * sc;
    }

    float m = -1e30f, l = 0.f;
    float acc[Dd];
#pragma unroll
    for (int d = 0; d < Dd; d++) acc[d] = 0.f;

    const int ntiles = 2 * (blockIdx.x + 1);   // kv tiles with j0 <= max row in CTA

    for (int tile = 0; tile < ntiles; tile++) {
        const int j0 = tile * 64;
        const float* kb = qkv + ((size_t)(b * Tt + j0)) * rs + Cc + h * Dd;
        const float* vb = kb + Cc;

        // cooperative load of K/V tiles (64 rows x 64 cols, float4)
#pragma unroll
        for (int kl = 0; kl < 8; kl++) {
            int idx = threadIdx.x + kl * 128;
            int r = idx >> 4, c4 = (idx & 15) * 4;
            *(float4*)&Ks[r][c4] = *(const float4*)(kb + (size_t)r * rs + c4);
            *(float4*)&Vs[r][c4] = *(const float4*)(vb + (size_t)r * rs + c4);
        }
        __syncthreads();

        if (j0 <= t) {                        // tile has at least one unmasked key
#pragma unroll 1
            for (int c = 0; c < 64; c += 16) {
                if (j0 + c > t) break;        // rest of tile fully masked

                float s[16];
                float mloc = -1e30f;
#pragma unroll
                for (int jj = 0; jj < 16; jj++) {
                    const float4* kr = (const float4*)Ks[c + jj];
                    float sum = 0.f;
#pragma unroll
                    for (int d4 = 0; d4 < 16; d4++) {
                        float4 kv = kr[d4];
                        sum = fmaf(q[4 * d4 + 0], kv.x, sum);
                        sum = fmaf(q[4 * d4 + 1], kv.y, sum);
                        sum = fmaf(q[4 * d4 + 2], kv.z, sum);
                        sum = fmaf(q[4 * d4 + 3], kv.w, sum);
                    }
                    sum = (j0 + c + jj <= t) ? sum : -1e30f;
                    s[jj] = sum;
                    mloc = fmaxf(mloc, sum);
                }

                float mnew  = fmaxf(m, mloc);
                float alpha = exp2f(m - mnew);
                l *= alpha;
#pragma unroll
                for (int d = 0; d < Dd; d++) acc[d] *= alpha;

#pragma unroll
                for (int jj = 0; jj < 16; jj++) {
                    float p = exp2f(s[jj] - mnew);
                    l += p;
                    const float4* vr = (const float4*)Vs[c + jj];
#pragma unroll
                    for (int d4 = 0; d4 < 16; d4++) {
                        float4 vv = vr[d4];
                        acc[4 * d4 + 0] = fmaf(p, vv.x, acc[4 * d4 + 0]);
                        acc[4 * d4 + 1] = fmaf(p, vv.y, acc[4 * d4 + 1]);
                        acc[4 * d4 + 2] = fmaf(p, vv.z, acc[4 * d4 + 2]);
                        acc[4 * d4 + 3] = fmaf(p, vv.w, acc[4 * d4 + 3]);
                    }
                }
                m = mnew;
            }
        }
        __syncthreads();
    }

    const float inv = 1.f / l;
    float* yp = y + ((size_t)(b * Tt + t)) * Cc + h * Dd;
#pragma unroll
    for (int d = 0; d < Dd; d += 4) {
        *(float4*)(yp + d) = make_float4(acc[d] * inv, acc[d + 1] * inv,
                                         acc[d + 2] * inv, acc[d + 3] * inv);
    }
}

// ---------------------------------------------------------------------------
extern "C" void kernel_launch(void* const* d_in, const int* in_sizes, int n_in,
                              void* d_out, int out_size) {
    const float* x     = (const float*)d_in[0];   // (B,T,C)
    const float* w_qkv = (const float*)d_in[1];   // (C, 3C)
    const float* w_out = (const float*)d_in[2];   // (C, C)
    float* out = (float*)d_out;                   // (B,T,C)

    float *qkv, *y;
    cudaGetSymbolAddress((void**)&qkv, g_qkv);
    cudaGetSymbolAddress((void**)&y,   g_y);

    // 1) qkv = x @ w_qkv           (8192 x 2304 x 768)
    sgemm128<<<dim3((3 * Cc) / 128, (Bb * Tt) / 128), 256>>>(x, w_qkv, qkv,
                                                             Bb * Tt, 3 * Cc, Cc);
    // 2) flash attention (causal)  -> y (B,T,C)
    attn_kernel<<<dim3(Tt / 128, Bb * Hh), 128>>>(qkv, y);
    // 3) out = y @ w_out           (8192 x 768 x 768)
    sgemm128<<<dim3(Cc / 128, (Bb * Tt) / 128), 256>>>(y, w_out, out,
                                                       Bb * Tt, Cc, Cc);
}

// round 3
// speedup vs baseline: 4.1262x; 4.1262x over previous
#include <cuda_runtime.h>
#include <cuda_bf16.h>
#include <cstdint>

#define Bb 2
#define Tt 4096
#define Cc 768
#define Hh 12
#define Dd 64

// ---------------------------------------------------------------------------
// Scratch (device globals: allocation-free per harness rules)
// ---------------------------------------------------------------------------
__device__ float g_qkv[(size_t)Bb * Tt * 3 * Cc];         // (B*T, 3C): [Q|K|V]
__device__ float g_y[(size_t)Bb * Tt * Cc];               // (B*T, C)
__device__ __nv_bfloat16 g_wqkvT_hi[(size_t)3 * Cc * Cc]; // w_qkv^T [N][K]
__device__ __nv_bfloat16 g_wqkvT_lo[(size_t)3 * Cc * Cc];
__device__ __nv_bfloat16 g_woutT_hi[(size_t)Cc * Cc];     // w_out^T [N][K]
__device__ __nv_bfloat16 g_woutT_lo[(size_t)Cc * Cc];

// ---------------------------------------------------------------------------
// Helpers: family-stable tensor path (mma.sync + ldmatrix), MUFU exp2
// ---------------------------------------------------------------------------
__device__ __forceinline__ uint32_t smem_u32(const void* p) {
    uint32_t a;
    asm("{ .reg .u64 t; cvta.to.shared.u64 t, %1; cvt.u32.u64 %0, t; }" : "=r"(a) : "l"(p));
    return a;
}
__device__ __forceinline__ void ldsm4(uint32_t r[4], uint32_t a) {
    asm volatile("ldmatrix.sync.aligned.m8n8.x4.shared.b16 {%0,%1,%2,%3}, [%4];"
                 : "=r"(r[0]), "=r"(r[1]), "=r"(r[2]), "=r"(r[3]) : "r"(a));
}
__device__ __forceinline__ void ldsm4t(uint32_t r[4], uint32_t a) {
    asm volatile("ldmatrix.sync.aligned.m8n8.x4.trans.shared.b16 {%0,%1,%2,%3}, [%4];"
                 : "=r"(r[0]), "=r"(r[1]), "=r"(r[2]), "=r"(r[3]) : "r"(a));
}
__device__ __forceinline__ void mma16816(float* c, const uint32_t* a, const uint32_t* b) {
    asm volatile("mma.sync.aligned.m16n8k16.row.col.f32.bf16.bf16.f32 "
                 "{%0,%1,%2,%3}, {%4,%5,%6,%7}, {%8,%9}, {%0,%1,%2,%3};"
                 : "+f"(c[0]), "+f"(c[1]), "+f"(c[2]), "+f"(c[3])
                 : "r"(a[0]), "r"(a[1]), "r"(a[2]), "r"(a[3]), "r"(b[0]), "r"(b[1]));
}
__device__ __forceinline__ float ex2(float x) {
    float y; asm("ex2.approx.f32 %0, %1;" : "=f"(y) : "f"(x)); return y;
}
__device__ __forceinline__ uint32_t bfbits(__nv_bfloat162 v) {
    uint32_t u; *(reinterpret_cast<__nv_bfloat162*>(&u)) = v; return u;
}

#define RSB 144   // padded smem row stride (bytes): 64 bf16 = 128B data + 16B pad

// ---------------------------------------------------------------------------
// Weight transpose + bf16 hi/lo split: W[K][N] fp32 -> T_hi/T_lo [N][K] bf16
// ---------------------------------------------------------------------------
__global__ __launch_bounds__(256) void transpose_split(const float* __restrict__ W,
                                                       __nv_bfloat16* __restrict__ Thi,
                                                       __nv_bfloat16* __restrict__ Tlo,
                                                       int K, int N) {
    __shared__ float tile[32][33];
    int n0 = blockIdx.x * 32, k0 = blockIdx.y * 32;
    int tx = threadIdx.x, ty = threadIdx.y;
#pragma unroll
    for (int i = 0; i < 4; i++)
        tile[ty + i * 8][tx] = W[(size_t)(k0 + ty + i * 8) * N + n0 + tx];
    __syncthreads();
#pragma unroll
    for (int i = 0; i < 4; i++) {
        float v = tile[tx][ty + i * 8];
        __nv_bfloat16 h = __float2bfloat16(v);
        __nv_bfloat16 l = __float2bfloat16(v - __bfloat162float(h));
        size_t o = (size_t)(n0 + ty + i * 8) * K + k0 + tx;
        Thi[o] = h;
        Tlo[o] = l;
    }
}

// ---------------------------------------------------------------------------
// HMMA bf16x3 GEMM: C[M,N] = A[M,K] (fp32, split in-kernel) @ WT[N,K] (pre-split)
// Block 128x128, BK=64, 8 warps (warp tile 32x64), double-buffered smem.
// Stage layout (bytes): Ah 0, Al 18432, Bh 36864, Bl 55296; stage size 73728.
// ---------------------------------------------------------------------------
#define GSTG 73728
__global__ __launch_bounds__(256, 1) void gemm_hmma(const float* __restrict__ A,
                                                    const __nv_bfloat16* __restrict__ Whi,
                                                    const __nv_bfloat16* __restrict__ Wlo,
                                                    float* __restrict__ C,
                                                    int M, int N, int K) {
    extern __shared__ __align__(128) char sm[];
    const int tid = threadIdx.x, lane = tid & 31, wid = tid >> 5;
    const int wm = (wid & 3) * 32, wn = (wid >> 2) * 64;
    const int crow = blockIdx.y * 128, ccol = blockIdx.x * 128;
    const uint32_t sb = smem_u32(sm);
    const int nch = K / 64;

    float acc[2][8][4];
#pragma unroll
    for (int i = 0; i < 2; i++)
#pragma unroll
        for (int j = 0; j < 8; j++)
#pragma unroll
            for (int e = 0; e < 4; e++) acc[i][j][e] = 0.f;

    float4 fa[8];
    uint4 fbh[4], fbl[4];

    auto LDGC = [&](int c) {
#pragma unroll
        for (int i = 0; i < 8; i++) {
            int idx = tid + i * 256, r = idx >> 4, c4 = (idx & 15) << 2;
            fa[i] = *(const float4*)(A + (size_t)(crow + r) * K + c * 64 + c4);
        }
#pragma unroll
        for (int i = 0; i < 4; i++) {
            int idx = tid + i * 256, r = idx >> 3, c16 = idx & 7;
            size_t o = (size_t)(ccol + r) * K + c * 64 + c16 * 8;
            fbh[i] = *(const uint4*)(Whi + o);
            fbl[i] = *(const uint4*)(Wlo + o);
        }
    };
    auto STSC = [&](int s) {
        char* base = sm + s * GSTG;
#pragma unroll
        for (int i = 0; i < 8; i++) {
            int idx = tid + i * 256, r = idx >> 4, c4 = (idx & 15) << 2;
            float4 v = fa[i];
            __nv_bfloat162 h01 = __floats2bfloat162_rn(v.x, v.y);
            __nv_bfloat162 h23 = __floats2bfloat162_rn(v.z, v.w);
            __nv_bfloat162 l01 = __floats2bfloat162_rn(v.x - __bfloat162float(h01.x),
                                                       v.y - __bfloat162float(h01.y));
            __nv_bfloat162 l23 = __floats2bfloat162_rn(v.z - __bfloat162float(h23.x),
                                                       v.w - __bfloat162float(h23.y));
            *(uint2*)(base + r * RSB + c4 * 2)         = make_uint2(bfbits(h01), bfbits(h23));
            *(uint2*)(base + 18432 + r * RSB + c4 * 2) = make_uint2(bfbits(l01), bfbits(l23));
        }
#pragma unroll
        for (int i = 0; i < 4; i++) {
            int idx = tid + i * 256, r = idx >> 3, c16 = idx & 7;
            *(uint4*)(base + 36864 + r * RSB + c16 * 16) = fbh[i];
            *(uint4*)(base + 55296 + r * RSB + c16 * 16) = fbl[i];
        }
    };
    auto MMAC = [&](int s) {
        const uint32_t sA = sb + s * GSTG;
        const uint32_t sB = sA + 36864;
#pragma unroll
        for (int ks = 0; ks < 4; ks++) {
            uint32_t ah[2][4], al[2][4];
#pragma unroll
            for (int mt = 0; mt < 2; mt++) {
                uint32_t ad = sA + (uint32_t)((wm + mt * 16 + (lane & 15)) * RSB +
                                              ks * 32 + ((lane & 16) ? 16 : 0));
                ldsm4(ah[mt], ad);
                ldsm4(al[mt], ad + 18432);
            }
#pragma unroll
            for (int q = 0; q < 4; q++) {
                uint32_t bd = sB + (uint32_t)((wn + q * 16 + (lane & 7) + ((lane >> 4) << 3)) * RSB +
                                              ks * 32 + ((lane & 8) ? 16 : 0));
                uint32_t bh[4], bl[4];
                ldsm4(bh, bd);
                ldsm4(bl, bd + 18432);
#pragma unroll
                for (int mt = 0; mt < 2; mt++) {
                    mma16816(acc[mt][2 * q],     ah[mt], bh);
                    mma16816(acc[mt][2 * q],     al[mt], bh);
                    mma16816(acc[mt][2 * q],     ah[mt], bl);
                    mma16816(acc[mt][2 * q + 1], ah[mt], bh + 2);
                    mma16816(acc[mt][2 * q + 1], al[mt], bh + 2);
                    mma16816(acc[mt][2 * q + 1], ah[mt], bl + 2);
                }
            }
        }
    };

    LDGC(0);
    STSC(0);
    __syncthreads();
    for (int c = 0; c < nch; c++) {
        if (c + 1 < nch) LDGC(c + 1);
        MMAC(c & 1);
        if (c + 1 < nch) STSC((c + 1) & 1);
        __syncthreads();
    }

#pragma unroll
    for (int mt = 0; mt < 2; mt++)
#pragma unroll
        for (int nt = 0; nt < 8; nt++) {
            int row = crow + wm + mt * 16 + (lane >> 2);
            int col = ccol + wn + nt * 8 + (lane & 3) * 2;
            *(float2*)(C + (size_t)row * N + col) = make_float2(acc[mt][nt][0], acc[mt][nt][1]);
            *(float2*)(C + (size_t)(row + 8) * N + col) = make_float2(acc[mt][nt][2], acc[mt][nt][3]);
        }
}

// ---------------------------------------------------------------------------
// HMMA causal flash attention. CTA = 128 query rows (8 warps x 16 rows),
// key tiles of 64. Q frags register-resident; bf16x3 for QK^T and PV.
// smem: phase 0: Qh 0, Ql 18432. loop: Kh 0, Kl 9216, Vh 18432, Vl 27648.
// ---------------------------------------------------------------------------
__global__ __launch_bounds__(256, 1) void attn_hmma(const float* __restrict__ qkv,
                                                    float* __restrict__ y) {
    __shared__ __align__(128) char sm[36864];
    const int tid = threadIdx.x, lane = tid & 31, wid = tid >> 5;
    const int bh = blockIdx.y, b = bh / Hh, h = bh % Hh;
    const int qt = (int)gridDim.x - 1 - (int)blockIdx.x;   // big tiles first
    const int q0 = qt * 128;
    const int m0 = wid * 16;
    const uint32_t sb = smem_u32(sm);
    const float sc = 0.125f * 1.44269504088896340736f;     // 1/sqrt(64) * log2(e)

    // ---- stage Q (scaled), split hi/lo ----
#pragma unroll
    for (int i = 0; i < 8; i++) {
        int idx = tid + i * 256, r = idx >> 4, c4 = (idx & 15) << 2;
        float4 v = *(const float4*)(qkv + (size_t)(b * Tt + q0 + r) * (3 * Cc) + h * Dd + c4);
        v.x *= sc; v.y *= sc; v.z *= sc; v.w *= sc;
        __nv_bfloat162 h01 = __floats2bfloat162_rn(v.x, v.y);
        __nv_bfloat162 h23 = __floats2bfloat162_rn(v.z, v.w);
        __nv_bfloat162 l01 = __floats2bfloat162_rn(v.x - __bfloat162float(h01.x),
                                                   v.y - __bfloat162float(h01.y));
        __nv_bfloat162 l23 = __floats2bfloat162_rn(v.z - __bfloat162float(h23.x),
                                                   v.w - __bfloat162float(h23.y));
        *(uint2*)(sm + r * RSB + c4 * 2)         = make_uint2(bfbits(h01), bfbits(h23));
        *(uint2*)(sm + 18432 + r * RSB + c4 * 2) = make_uint2(bfbits(l01), bfbits(l23));
    }
    __syncthreads();
    uint32_t qh[4][4], ql[4][4];
#pragma unroll
    for (int ks = 0; ks < 4; ks++) {
        uint32_t ad = sb + (uint32_t)((m0 + (lane & 15)) * RSB + ks * 32 + ((lane & 16) ? 16 : 0));
        ldsm4(qh[ks], ad);
        ldsm4(ql[ks], ad + 18432);
    }
    __syncthreads();

    float o[8][4];
#pragma unroll
    for (int j = 0; j < 8; j++)
#pragma unroll
        for (int e = 0; e < 4; e++) o[j][e] = 0.f;
    float m1 = -1e30f, m2 = -1e30f, l1 = 0.f, l2 = 0.f;
    const int nkt = 2 * qt + 2;

    for (int kt = 0; kt < nkt; kt++) {
        // ---- stage K, V (split hi/lo) ----
#pragma unroll
        for (int i = 0; i < 4; i++) {
            int idx = tid + i * 256, r = idx >> 4, c4 = (idx & 15) << 2;
            const float* kp = qkv + (size_t)(b * Tt + kt * 64 + r) * (3 * Cc) + Cc + h * Dd + c4;
            float4 kv = *(const float4*)kp;
            float4 vv = *(const float4*)(kp + Cc);
            __nv_bfloat162 kh01 = __floats2bfloat162_rn(kv.x, kv.y);
            __nv_bfloat162 kh23 = __floats2bfloat162_rn(kv.z, kv.w);
            __nv_bfloat162 kl01 = __floats2bfloat162_rn(kv.x - __bfloat162float(kh01.x),
                                                        kv.y - __bfloat162float(kh01.y));
            __nv_bfloat162 kl23 = __floats2bfloat162_rn(kv.z - __bfloat162float(kh23.x),
                                                        kv.w - __bfloat162float(kh23.y));
            __nv_bfloat162 vh01 = __floats2bfloat162_rn(vv.x, vv.y);
            __nv_bfloat162 vh23 = __floats2bfloat162_rn(vv.z, vv.w);
            __nv_bfloat162 vl01 = __floats2bfloat162_rn(vv.x - __bfloat162float(vh01.x),
                                                        vv.y - __bfloat162float(vh01.y));
            __nv_bfloat162 vl23 = __floats2bfloat162_rn(vv.z - __bfloat162float(vh23.x),
                                                        vv.w - __bfloat162float(vh23.y));
            *(uint2*)(sm + r * RSB + c4 * 2)         = make_uint2(bfbits(kh01), bfbits(kh23));
            *(uint2*)(sm + 9216 + r * RSB + c4 * 2)  = make_uint2(bfbits(kl01), bfbits(kl23));
            *(uint2*)(sm + 18432 + r * RSB + c4 * 2) = make_uint2(bfbits(vh01), bfbits(vh23));
            *(uint2*)(sm + 27648 + r * RSB + c4 * 2) = make_uint2(bfbits(vl01), bfbits(vl23));
        }
        __syncthreads();

        // ---- S = Q @ K^T (bf16x3) ----
        float cS[8][4];
#pragma unroll
        for (int j = 0; j < 8; j++)
#pragma unroll
            for (int e = 0; e < 4; e++) cS[j][e] = 0.f;
#pragma unroll
        for (int ks = 0; ks < 4; ks++) {
#pragma unroll
            for (int q2 = 0; q2 < 4; q2++) {
                uint32_t bd = sb + (uint32_t)((q2 * 16 + (lane & 7) + ((lane >> 4) << 3)) * RSB +
                                              ks * 32 + ((lane & 8) ? 16 : 0));
                uint32_t kh4[4], kl4[4];
                ldsm4(kh4, bd);
                ldsm4(kl4, bd + 9216);
                mma16816(cS[2 * q2],     qh[ks], kh4);
                mma16816(cS[2 * q2],     ql[ks], kh4);
                mma16816(cS[2 * q2],     qh[ks], kl4);
                mma16816(cS[2 * q2 + 1], qh[ks], kh4 + 2);
                mma16816(cS[2 * q2 + 1], ql[ks], kh4 + 2);
                mma16816(cS[2 * q2 + 1], qh[ks], kl4 + 2);
            }
        }

        // ---- causal mask (only last two key tiles can cross the diagonal) ----
        if (kt >= 2 * qt) {
            int r1 = q0 + m0 + (lane >> 2);
#pragma unroll
            for (int nt = 0; nt < 8; nt++) {
                int k0c = kt * 64 + nt * 8 + (lane & 3) * 2;
                if (k0c     > r1)     cS[nt][0] = -1e30f;
                if (k0c + 1 > r1)     cS[nt][1] = -1e30f;
                if (k0c     > r1 + 8) cS[nt][2] = -1e30f;
                if (k0c + 1 > r1 + 8) cS[nt][3] = -1e30f;
            }
        }

        // ---- online softmax (rows g and g+8 per thread-quad) ----
        float mx1 = -1e30f, mx2 = -1e30f;
#pragma unroll
        for (int nt = 0; nt < 8; nt++) {
            mx1 = fmaxf(mx1, fmaxf(cS[nt][0], cS[nt][1]));
            mx2 = fmaxf(mx2, fmaxf(cS[nt][2], cS[nt][3]));
        }
        mx1 = fmaxf(mx1, __shfl_xor_sync(0xffffffffu, mx1, 1));
        mx1 = fmaxf(mx1, __shfl_xor_sync(0xffffffffu, mx1, 2));
        mx2 = fmaxf(mx2, __shfl_xor_sync(0xffffffffu, mx2, 1));
        mx2 = fmaxf(mx2, __shfl_xor_sync(0xffffffffu, mx2, 2));
        float mn1 = fmaxf(m1, mx1), mn2 = fmaxf(m2, mx2);
        float a1 = ex2(m1 - mn1), a2 = ex2(m2 - mn2);
        float s1 = 0.f, s2 = 0.f;
        uint32_t ph[8], pl[8], ph8[8], pl8[8];
#pragma unroll
        for (int nt = 0; nt < 8; nt++) {
            float p0 = ex2(cS[nt][0] - mn1), p1 = ex2(cS[nt][1] - mn1);
            float p2 = ex2(cS[nt][2] - mn2), p3 = ex2(cS[nt][3] - mn2);
            s1 += p0 + p1;
            s2 += p2 + p3;
            __nv_bfloat162 hh = __floats2bfloat162_rn(p0, p1);
            __nv_bfloat162 ll = __floats2bfloat162_rn(p0 - __bfloat162float(hh.x),
                                                      p1 - __bfloat162float(hh.y));
            ph[nt] = bfbits(hh);
            pl[nt] = bfbits(ll);
            hh = __floats2bfloat162_rn(p2, p3);
            ll = __floats2bfloat162_rn(p2 - __bfloat162float(hh.x),
                                       p3 - __bfloat162float(hh.y));
            ph8[nt] = bfbits(hh);
            pl8[nt] = bfbits(ll);
        }
        s1 += __shfl_xor_sync(0xffffffffu, s1, 1);
        s1 += __shfl_xor_sync(0xffffffffu, s1, 2);
        s2 += __shfl_xor_sync(0xffffffffu, s2, 1);
        s2 += __shfl_xor_sync(0xffffffffu, s2, 2);
        l1 = l1 * a1 + s1;
        l2 = l2 * a2 + s2;
#pragma unroll
        for (int nt = 0; nt < 8; nt++) {
            o[nt][0] *= a1; o[nt][1] *= a1;
            o[nt][2] *= a2; o[nt][3] *= a2;
        }
        m1 = mn1;
        m2 = mn2;

        // ---- O += P @ V (bf16x3, P from registers, V via ldmatrix.trans) ----
#pragma unroll
        for (int kk = 0; kk < 4; kk++) {
            uint32_t ah4[4] = {ph[2 * kk], ph8[2 * kk], ph[2 * kk + 1], ph8[2 * kk + 1]};
            uint32_t al4[4] = {pl[2 * kk], pl8[2 * kk], pl[2 * kk + 1], pl8[2 * kk + 1]};
#pragma unroll
            for (int q2 = 0; q2 < 4; q2++) {
                uint32_t vd = sb + 18432u + (uint32_t)((kk * 16 + (lane & 15)) * RSB +
                                                       (q2 * 16 + ((lane & 16) ? 8 : 0)) * 2);
                uint32_t vh4[4], vl4[4];
                ldsm4t(vh4, vd);
                ldsm4t(vl4, vd + 9216);
                mma16816(o[2 * q2],     ah4, vh4);
                mma16816(o[2 * q2],     al4, vh4);
                mma16816(o[2 * q2],     ah4, vl4);
                mma16816(o[2 * q2 + 1], ah4, vh4 + 2);
                mma16816(o[2 * q2 + 1], al4, vh4 + 2);
                mma16816(o[2 * q2 + 1], ah4, vl4 + 2);
            }
        }
        __syncthreads();
    }

    // ---- epilogue: O /= l, store to y ----
    float i1 = 1.f / l1, i2 = 1.f / l2;
    int row = q0 + m0 + (lane >> 2);
#pragma unroll
    for (int nt = 0; nt < 8; nt++) {
        int col = h * Dd + nt * 8 + (lane & 3) * 2;
        *(float2*)(y + (size_t)(b * Tt + row) * Cc + col) =
            make_float2(o[nt][0] * i1, o[nt][1] * i1);
        *(float2*)(y + (size_t)(b * Tt + row + 8) * Cc + col) =
            make_float2(o[nt][2] * i2, o[nt][3] * i2);
    }
}

// ---------------------------------------------------------------------------
extern "C" void kernel_launch(void* const* d_in, const int* in_sizes, int n_in,
                              void* d_out, int out_size) {
    const float* x     = (const float*)d_in[0];
    const float* w_qkv = (const float*)d_in[1];
    const float* w_out = (const float*)d_in[2];
    float* out = (float*)d_out;

    float *qkv, *y;
    __nv_bfloat16 *wqh, *wql, *woh, *wol;
    cudaGetSymbolAddress((void**)&qkv, g_qkv);
    cudaGetSymbolAddress((void**)&y,   g_y);
    cudaGetSymbolAddress((void**)&wqh, g_wqkvT_hi);
    cudaGetSymbolAddress((void**)&wql, g_wqkvT_lo);
    cudaGetSymbolAddress((void**)&woh, g_woutT_hi);
    cudaGetSymbolAddress((void**)&wol, g_woutT_lo);

    cudaFuncSetAttribute(gemm_hmma, cudaFuncAttributeMaxDynamicSharedMemorySize, 2 * GSTG);

    // 0) weight transpose + bf16 hi/lo split
    transpose_split<<<dim3((3 * Cc) / 32, Cc / 32), dim3(32, 8)>>>(w_qkv, wqh, wql, Cc, 3 * Cc);
    transpose_split<<<dim3(Cc / 32, Cc / 32), dim3(32, 8)>>>(w_out, woh, wol, Cc, Cc);

    // 1) qkv = x @ w_qkv
    gemm_hmma<<<dim3((3 * Cc) / 128, (Bb * Tt) / 128), 256, 2 * GSTG>>>(
        x, wqh, wql, qkv, Bb * Tt, 3 * Cc, Cc);

    // 2) causal flash attention (HMMA)
    attn_hmma<<<dim3(Tt / 128, Bb * Hh), 256>>>(qkv, y);

    // 3) out = y @ w_out
    gemm_hmma<<<dim3(Cc / 128, (Bb * Tt) / 128), 256, 2 * GSTG>>>(
        y, woh, wol, out, Bb * Tt, Cc, Cc);
}

// round 4
// speedup vs baseline: 4.3247x; 1.0481x over previous
#include <cuda_runtime.h>
#include <cuda_bf16.h>
#include <cstdint>

#define Bb 2
#define Tt 4096
#define Cc 768
#define Hh 12
#define Dd 64

#define NTOK   (Bb * Tt)          // 8192
#define RSB    144                // padded smem row stride: 128B data + 16B
#define GSTG   73728              // GEMM/attn stage: 4 arrays * 128(64)*RSB
#define SCL    0.18033688011112042f   // (1/sqrt(64)) * log2(e)

// ---------------------------------------------------------------------------
// Scratch (device globals)
// ---------------------------------------------------------------------------
__device__ __nv_bfloat16 g_xh[(size_t)NTOK * Cc], g_xl[(size_t)NTOK * Cc];
__device__ __nv_bfloat16 g_qh[(size_t)Bb * Hh * Tt * Dd], g_ql[(size_t)Bb * Hh * Tt * Dd];
__device__ __nv_bfloat16 g_kh[(size_t)Bb * Hh * Tt * Dd], g_kl[(size_t)Bb * Hh * Tt * Dd];
__device__ __nv_bfloat16 g_vh[(size_t)Bb * Hh * Tt * Dd], g_vl[(size_t)Bb * Hh * Tt * Dd];
__device__ __nv_bfloat16 g_yh[(size_t)NTOK * Cc], g_yl[(size_t)NTOK * Cc];
__device__ __nv_bfloat16 g_wqkvT_hi[(size_t)3 * Cc * Cc], g_wqkvT_lo[(size_t)3 * Cc * Cc];
__device__ __nv_bfloat16 g_woutT_hi[(size_t)Cc * Cc],     g_woutT_lo[(size_t)Cc * Cc];

// ---------------------------------------------------------------------------
// Helpers
// ---------------------------------------------------------------------------
__device__ __forceinline__ uint32_t smem_u32(const void* p) {
    uint32_t a;
    asm("{ .reg .u64 t; cvta.to.shared.u64 t, %1; cvt.u32.u64 %0, t; }" : "=r"(a) : "l"(p));
    return a;
}
__device__ __forceinline__ void ldsm4(uint32_t r[4], uint32_t a) {
    asm volatile("ldmatrix.sync.aligned.m8n8.x4.shared.b16 {%0,%1,%2,%3}, [%4];"
                 : "=r"(r[0]), "=r"(r[1]), "=r"(r[2]), "=r"(r[3]) : "r"(a));
}
__device__ __forceinline__ void ldsm4t(uint32_t r[4], uint32_t a) {
    asm volatile("ldmatrix.sync.aligned.m8n8.x4.trans.shared.b16 {%0,%1,%2,%3}, [%4];"
                 : "=r"(r[0]), "=r"(r[1]), "=r"(r[2]), "=r"(r[3]) : "r"(a));
}
__device__ __forceinline__ void mma16816(float* c, const uint32_t* a, const uint32_t* b) {
    asm volatile("mma.sync.aligned.m16n8k16.row.col.f32.bf16.bf16.f32 "
                 "{%0,%1,%2,%3}, {%4,%5,%6,%7}, {%8,%9}, {%0,%1,%2,%3};"
                 : "+f"(c[0]), "+f"(c[1]), "+f"(c[2]), "+f"(c[3])
                 : "r"(a[0]), "r"(a[1]), "r"(a[2]), "r"(a[3]), "r"(b[0]), "r"(b[1]));
}
__device__ __forceinline__ float ex2(float x) {
    float y; asm("ex2.approx.f32 %0, %1;" : "=f"(y) : "f"(x)); return y;
}
__device__ __forceinline__ uint32_t bfbits(__nv_bfloat162 v) {
    uint32_t u; *(reinterpret_cast<__nv_bfloat162*>(&u)) = v; return u;
}
__device__ __forceinline__ void split2(float a, float b, uint32_t& hi, uint32_t& lo) {
    __nv_bfloat162 h = __floats2bfloat162_rn(a, b);
    __nv_bfloat162 l = __floats2bfloat162_rn(a - __bfloat162float(h.x),
                                             b - __bfloat162float(h.y));
    hi = bfbits(h); lo = bfbits(l);
}
__device__ __forceinline__ void cpa16(uint32_t dst, const void* src) {
    asm volatile("cp.async.cg.shared.global [%0], [%1], 16;" :: "r"(dst), "l"(src));
}
#define CP_COMMIT() asm volatile("cp.async.commit_group;" ::: "memory")
#define CP_WAIT(n)  asm volatile("cp.async.wait_group %0;" :: "n"(n) : "memory")

// ---------------------------------------------------------------------------
// Prep kernels
// ---------------------------------------------------------------------------
__global__ __launch_bounds__(256) void transpose_split(const float* __restrict__ W,
                                                       __nv_bfloat16* __restrict__ Thi,
                                                       __nv_bfloat16* __restrict__ Tlo,
                                                       int K, int N) {
    __shared__ float tile[32][33];
    int n0 = blockIdx.x * 32, k0 = blockIdx.y * 32;
    int tx = threadIdx.x, ty = threadIdx.y;
#pragma unroll
    for (int i = 0; i < 4; i++)
        tile[ty + i * 8][tx] = W[(size_t)(k0 + ty + i * 8) * N + n0 + tx];
    __syncthreads();
#pragma unroll
    for (int i = 0; i < 4; i++) {
        float v = tile[tx][ty + i * 8];
        __nv_bfloat16 h = __float2bfloat16(v);
        __nv_bfloat16 l = __float2bfloat16(v - __bfloat162float(h));
        size_t o = (size_t)(n0 + ty + i * 8) * K + k0 + tx;
        Thi[o] = h; Tlo[o] = l;
    }
}

__global__ __launch_bounds__(256) void split_x(const float* __restrict__ X,
                                               __nv_bfloat16* __restrict__ Xh,
                                               __nv_bfloat16* __restrict__ Xl) {
    int i = blockIdx.x * 256 + threadIdx.x;      // one float4 per thread
    float4 v = ((const float4*)X)[i];
    uint32_t h01, l01, h23, l23;
    split2(v.x, v.y, h01, l01);
    split2(v.z, v.w, h23, l23);
    ((uint2*)Xh)[i] = make_uint2(h01, h23);
    ((uint2*)Xl)[i] = make_uint2(l01, l23);
}

// ---------------------------------------------------------------------------
// HMMA bf16x3 GEMM, pre-split operands, cp.async 3-stage pipeline.
// Block 128x128, BK=64, 8 warps (32x64 warp tile).
// Stage: Ah 0, Al 18432, Bh 36864, Bl 55296. 3 stages = 221184 B dyn smem.
// mode 0: qkv epilogue -> split head-major Q(scaled)/K/V. mode 1: fp32 C.
// ---------------------------------------------------------------------------
__global__ __launch_bounds__(256, 1) void gemm_hmma(
    const __nv_bfloat16* __restrict__ Ah, const __nv_bfloat16* __restrict__ Al,
    const __nv_bfloat16* __restrict__ Wh, const __nv_bfloat16* __restrict__ Wl,
    float* __restrict__ Cout,
    __nv_bfloat16* __restrict__ Qh, __nv_bfloat16* __restrict__ Ql,
    __nv_bfloat16* __restrict__ Kh, __nv_bfloat16* __restrict__ Kl,
    __nv_bfloat16* __restrict__ Vh, __nv_bfloat16* __restrict__ Vl,
    int M, int N, int K, int mode) {
    extern __shared__ __align__(128) char sm[];
    const int tid = threadIdx.x, lane = tid & 31, wid = tid >> 5;
    const int wm = (wid & 3) * 32, wn = (wid >> 2) * 64;
    const int crow = blockIdx.y * 128, ccol = blockIdx.x * 128;
    const uint32_t sb = smem_u32(sm);
    const int nch = K / 64;

    float acc[2][8][4];
#pragma unroll
    for (int i = 0; i < 2; i++)
#pragma unroll
        for (int j = 0; j < 8; j++)
#pragma unroll
            for (int e = 0; e < 4; e++) acc[i][j][e] = 0.f;

    auto STAGE = [&](int c, int s) {
        uint32_t sbuf = sb + (uint32_t)s * GSTG;
        const __nv_bfloat16* a0 = Ah + (size_t)crow * K + c * 64;
        const __nv_bfloat16* a1 = Al + (size_t)crow * K + c * 64;
        const __nv_bfloat16* b0 = Wh + (size_t)ccol * K + c * 64;
        const __nv_bfloat16* b1 = Wl + (size_t)ccol * K + c * 64;
#pragma unroll
        for (int i = 0; i < 4; i++) {
            int idx = tid + i * 256, r = idx >> 3, ch = idx & 7;
            size_t go = (size_t)r * K + ch * 8;
            uint32_t so = (uint32_t)(r * RSB + ch * 16);
            cpa16(sbuf + so,          a0 + go);
            cpa16(sbuf + 18432 + so,  a1 + go);
            cpa16(sbuf + 36864 + so,  b0 + go);
            cpa16(sbuf + 55296 + so,  b1 + go);
        }
    };
    auto MMAC = [&](int s) {
        const uint32_t sA = sb + (uint32_t)s * GSTG;
        const uint32_t sB = sA + 36864;
#pragma unroll
        for (int ks = 0; ks < 4; ks++) {
            uint32_t ah[2][4], al[2][4];
#pragma unroll
            for (int mt = 0; mt < 2; mt++) {
                uint32_t ad = sA + (uint32_t)((wm + mt * 16 + (lane & 15)) * RSB +
                                              ks * 32 + ((lane & 16) ? 16 : 0));
                ldsm4(ah[mt], ad);
                ldsm4(al[mt], ad + 18432);
            }
#pragma unroll
            for (int q = 0; q < 4; q++) {
                uint32_t bd = sB + (uint32_t)((wn + q * 16 + (lane & 7) + ((lane >> 4) << 3)) * RSB +
                                              ks * 32 + ((lane & 8) ? 16 : 0));
                uint32_t bh[4], bl[4];
                ldsm4(bh, bd);
                ldsm4(bl, bd + 18432);
#pragma unroll
                for (int mt = 0; mt < 2; mt++) {
                    mma16816(acc[mt][2 * q],     ah[mt], bh);
                    mma16816(acc[mt][2 * q],     al[mt], bh);
                    mma16816(acc[mt][2 * q],     ah[mt], bl);
                    mma16816(acc[mt][2 * q + 1], ah[mt], bh + 2);
                    mma16816(acc[mt][2 * q + 1], al[mt], bh + 2);
                    mma16816(acc[mt][2 * q + 1], ah[mt], bl + 2);
                }
            }
        }
    };

    STAGE(0, 0); CP_COMMIT();
    STAGE(1, 1); CP_COMMIT();
    for (int c = 0; c < nch; c++) {
        if (c + 2 < nch) STAGE(c + 2, (c + 2) % 3);
        CP_COMMIT();
        CP_WAIT(2);
        __syncthreads();
        MMAC(c % 3);
        __syncthreads();
    }

    if (mode == 1) {
#pragma unroll
        for (int mt = 0; mt < 2; mt++)
#pragma unroll
            for (int nt = 0; nt < 8; nt++) {
                int row = crow + wm + mt * 16 + (lane >> 2);
                int col = ccol + wn + nt * 8 + (lane & 3) * 2;
                *(float2*)(Cout + (size_t)row * N + col) =
                    make_float2(acc[mt][nt][0], acc[mt][nt][1]);
                *(float2*)(Cout + (size_t)(row + 8) * N + col) =
                    make_float2(acc[mt][nt][2], acc[mt][nt][3]);
            }
    } else {
        __nv_bfloat16* PH[3] = {Qh, Kh, Vh};
        __nv_bfloat16* PL[3] = {Ql, Kl, Vl};
        const int selb = ccol / Cc;            // Cc % 128 == 0: uniform per block
        const float scale = (selb == 0) ? SCL : 1.f;
        __nv_bfloat16* ph = PH[selb];
        __nv_bfloat16* pl = PL[selb];
#pragma unroll
        for (int mt = 0; mt < 2; mt++)
#pragma unroll
            for (int nt = 0; nt < 8; nt++) {
                int row = crow + wm + mt * 16 + (lane >> 2);
                int col = ccol + wn + nt * 8 + (lane & 3) * 2;
                int rem = col - selb * Cc, h = rem >> 6, d = rem & 63;
#pragma unroll
                for (int half = 0; half < 2; half++) {
                    int r2 = row + half * 8;
                    int b = r2 >> 12, t = r2 & 4095;
                    size_t off = ((size_t)(b * Hh + h) * Tt + t) * Dd + d;
                    uint32_t hi, lo;
                    split2(acc[mt][nt][2 * half] * scale,
                           acc[mt][nt][2 * half + 1] * scale, hi, lo);
                    *(uint32_t*)(ph + off) = hi;
                    *(uint32_t*)(pl + off) = lo;
                }
            }
    }
}

// ---------------------------------------------------------------------------
// HMMA causal flash attention. 128 query rows/CTA (8 warps x 16), 64-key tiles,
// pre-split bf16 operands, cp.async double-buffered K/V staging.
// Stage: Kh 0, Kl 9216, Vh 18432, Vl 27648 (36864 B); 2 stages = 73728 B.
// ---------------------------------------------------------------------------
__global__ __launch_bounds__(256, 1) void attn_hmma(
    const __nv_bfloat16* __restrict__ Qh_, const __nv_bfloat16* __restrict__ Ql_,
    const __nv_bfloat16* __restrict__ Kh_, const __nv_bfloat16* __restrict__ Kl_,
    const __nv_bfloat16* __restrict__ Vh_, const __nv_bfloat16* __restrict__ Vl_,
    __nv_bfloat16* __restrict__ Yh, __nv_bfloat16* __restrict__ Yl) {
    extern __shared__ __align__(128) char sm[];
    const int tid = threadIdx.x, lane = tid & 31, wid = tid >> 5;
    const int bh = blockIdx.y, b = bh / Hh, h = bh % Hh;
    const int qt = (int)gridDim.x - 1 - (int)blockIdx.x;   // big tiles first
    const int q0 = qt * 128;
    const int m0 = wid * 16;
    const uint32_t sb = smem_u32(sm);
    const size_t hb = (size_t)bh * Tt;

    // ---- stage Q (already scaled+split) into buf0, load fragments ----
    {
        const __nv_bfloat16* qg0 = Qh_ + (hb + q0) * Dd;
        const __nv_bfloat16* qg1 = Ql_ + (hb + q0) * Dd;
#pragma unroll
        for (int i = 0; i < 4; i++) {
            int idx = tid + i * 256, r = idx >> 3, ch = idx & 7;
            *(uint4*)(sm + r * RSB + ch * 16)         = *(const uint4*)(qg0 + r * Dd + ch * 8);
            *(uint4*)(sm + 18432 + r * RSB + ch * 16) = *(const uint4*)(qg1 + r * Dd + ch * 8);
        }
    }
    __syncthreads();
    uint32_t qh[4][4], ql[4][4];
#pragma unroll
    for (int ks = 0; ks < 4; ks++) {
        uint32_t ad = sb + (uint32_t)((m0 + (lane & 15)) * RSB + ks * 32 + ((lane & 16) ? 16 : 0));
        ldsm4(qh[ks], ad);
        ldsm4(ql[ks], ad + 18432);
    }
    __syncthreads();

    auto STAGEKV = [&](int kt, int s) {
        uint32_t sbuf = sb + (uint32_t)s * 36864;
        const __nv_bfloat16* k0 = Kh_ + (hb + kt * 64) * Dd;
        const __nv_bfloat16* k1 = Kl_ + (hb + kt * 64) * Dd;
        const __nv_bfloat16* v0 = Vh_ + (hb + kt * 64) * Dd;
        const __nv_bfloat16* v1 = Vl_ + (hb + kt * 64) * Dd;
#pragma unroll
        for (int i = 0; i < 2; i++) {
            int idx = tid + i * 256, r = idx >> 3, ch = idx & 7;
            size_t go = (size_t)r * Dd + ch * 8;
            uint32_t so = (uint32_t)(r * RSB + ch * 16);
            cpa16(sbuf + so,          k0 + go);
            cpa16(sbuf + 9216 + so,   k1 + go);
            cpa16(sbuf + 18432 + so,  v0 + go);
            cpa16(sbuf + 27648 + so,  v1 + go);
        }
    };

    float o[8][4];
#pragma unroll
    for (int j = 0; j < 8; j++)
#pragma unroll
        for (int e = 0; e < 4; e++) o[j][e] = 0.f;
    float m1 = -1e30f, m2 = -1e30f, l1 = 0.f, l2 = 0.f;
    const int nkt = 2 * qt + 2;

    STAGEKV(0, 0); CP_COMMIT();
    STAGEKV(1, 1); CP_COMMIT();

    for (int kt = 0; kt < nkt; kt++) {
        CP_WAIT(1);
        __syncthreads();
        const uint32_t sbuf = sb + (uint32_t)(kt & 1) * 36864;

        // ---- S = Q @ K^T (bf16x3) ----
        float cS[8][4];
#pragma unroll
        for (int j = 0; j < 8; j++)
#pragma unroll
            for (int e = 0; e < 4; e++) cS[j][e] = 0.f;
#pragma unroll
        for (int ks = 0; ks < 4; ks++) {
#pragma unroll
            for (int q2 = 0; q2 < 4; q2++) {
                uint32_t bd = sbuf + (uint32_t)((q2 * 16 + (lane & 7) + ((lane >> 4) << 3)) * RSB +
                                                ks * 32 + ((lane & 8) ? 16 : 0));
                uint32_t kh4[4], kl4[4];
                ldsm4(kh4, bd);
                ldsm4(kl4, bd + 9216);
                mma16816(cS[2 * q2],     qh[ks], kh4);
                mma16816(cS[2 * q2],     ql[ks], kh4);
                mma16816(cS[2 * q2],     qh[ks], kl4);
                mma16816(cS[2 * q2 + 1], qh[ks], kh4 + 2);
                mma16816(cS[2 * q2 + 1], ql[ks], kh4 + 2);
                mma16816(cS[2 * q2 + 1], qh[ks], kl4 + 2);
            }
        }

        // ---- causal mask ----
        if (kt >= 2 * qt) {
            int r1 = q0 + m0 + (lane >> 2);
#pragma unroll
            for (int nt = 0; nt < 8; nt++) {
                int k0c = kt * 64 + nt * 8 + (lane & 3) * 2;
                if (k0c     > r1)     cS[nt][0] = -1e30f;
                if (k0c + 1 > r1)     cS[nt][1] = -1e30f;
                if (k0c     > r1 + 8) cS[nt][2] = -1e30f;
                if (k0c + 1 > r1 + 8) cS[nt][3] = -1e30f;
            }
        }

        // ---- online softmax ----
        float mx1 = -1e30f, mx2 = -1e30f;
#pragma unroll
        for (int nt = 0; nt < 8; nt++) {
            mx1 = fmaxf(mx1, fmaxf(cS[nt][0], cS[nt][1]));
            mx2 = fmaxf(mx2, fmaxf(cS[nt][2], cS[nt][3]));
        }
        mx1 = fmaxf(mx1, __shfl_xor_sync(0xffffffffu, mx1, 1));
        mx1 = fmaxf(mx1, __shfl_xor_sync(0xffffffffu, mx1, 2));
        mx2 = fmaxf(mx2, __shfl_xor_sync(0xffffffffu, mx2, 1));
        mx2 = fmaxf(mx2, __shfl_xor_sync(0xffffffffu, mx2, 2));
        float mn1 = fmaxf(m1, mx1), mn2 = fmaxf(m2, mx2);
        float a1 = ex2(m1 - mn1), a2 = ex2(m2 - mn2);
        float s1 = 0.f, s2 = 0.f;
        uint32_t ph[8], pl[8], ph8[8], pl8[8];
#pragma unroll
        for (int nt = 0; nt < 8; nt++) {
            float p0 = ex2(cS[nt][0] - mn1), p1 = ex2(cS[nt][1] - mn1);
            float p2 = ex2(cS[nt][2] - mn2), p3 = ex2(cS[nt][3] - mn2);
            s1 += p0 + p1;
            s2 += p2 + p3;
            split2(p0, p1, ph[nt], pl[nt]);
            split2(p2, p3, ph8[nt], pl8[nt]);
        }
        s1 += __shfl_xor_sync(0xffffffffu, s1, 1);
        s1 += __shfl_xor_sync(0xffffffffu, s1, 2);
        s2 += __shfl_xor_sync(0xffffffffu, s2, 1);
        s2 += __shfl_xor_sync(0xffffffffu, s2, 2);
        l1 = l1 * a1 + s1;
        l2 = l2 * a2 + s2;
#pragma unroll
        for (int nt = 0; nt < 8; nt++) {
            o[nt][0] *= a1; o[nt][1] *= a1;
            o[nt][2] *= a2; o[nt][3] *= a2;
        }
        m1 = mn1;
        m2 = mn2;

        // ---- O += P @ V (bf16x3) ----
#pragma unroll
        for (int kk = 0; kk < 4; kk++) {
            uint32_t ah4[4] = {ph[2 * kk], ph8[2 * kk], ph[2 * kk + 1], ph8[2 * kk + 1]};
            uint32_t al4[4] = {pl[2 * kk], pl8[2 * kk], pl[2 * kk + 1], pl8[2 * kk + 1]};
#pragma unroll
            for (int q2 = 0; q2 < 4; q2++) {
                uint32_t vd = sbuf + 18432u + (uint32_t)((kk * 16 + (lane & 15)) * RSB +
                                                         (q2 * 16 + ((lane & 16) ? 8 : 0)) * 2);
                uint32_t vh4[4], vl4[4];
                ldsm4t(vh4, vd);
                ldsm4t(vl4, vd + 9216);
                mma16816(o[2 * q2],     ah4, vh4);
                mma16816(o[2 * q2],     al4, vh4);
                mma16816(o[2 * q2],     ah4, vl4);
                mma16816(o[2 * q2 + 1], ah4, vh4 + 2);
                mma16816(o[2 * q2 + 1], al4, vh4 + 2);
                mma16816(o[2 * q2 + 1], ah4, vl4 + 2);
            }
        }
        __syncthreads();

        if (kt + 2 < nkt) STAGEKV(kt + 2, kt & 1);
        CP_COMMIT();
    }

    // ---- epilogue: O /= l, split, store y as bf16 hi/lo (token-major) ----
    float i1 = 1.f / l1, i2 = 1.f / l2;
    int row = q0 + m0 + (lane >> 2);
#pragma unroll
    for (int nt = 0; nt < 8; nt++) {
        int col = h * Dd + nt * 8 + (lane & 3) * 2;
        size_t off1 = ((size_t)b * Tt + row) * Cc + col;
        size_t off2 = off1 + (size_t)8 * Cc;
        uint32_t hi, lo;
        split2(o[nt][0] * i1, o[nt][1] * i1, hi, lo);
        *(uint32_t*)(Yh + off1) = hi;
        *(uint32_t*)(Yl + off1) = lo;
        split2(o[nt][2] * i2, o[nt][3] * i2, hi, lo);
        *(uint32_t*)(Yh + off2) = hi;
        *(uint32_t*)(Yl + off2) = lo;
    }
}

// ---------------------------------------------------------------------------
extern "C" void kernel_launch(void* const* d_in, const int* in_sizes, int n_in,
                              void* d_out, int out_size) {
    const float* x     = (const float*)d_in[0];
    const float* w_qkv = (const float*)d_in[1];
    const float* w_out = (const float*)d_in[2];
    float* out = (float*)d_out;

    __nv_bfloat16 *xh, *xl, *qh, *ql, *kh, *kl, *vh, *vl, *yh, *yl;
    __nv_bfloat16 *wqh, *wql, *woh, *wol;
    cudaGetSymbolAddress((void**)&xh, g_xh);   cudaGetSymbolAddress((void**)&xl, g_xl);
    cudaGetSymbolAddress((void**)&qh, g_qh);   cudaGetSymbolAddress((void**)&ql, g_ql);
    cudaGetSymbolAddress((void**)&kh, g_kh);   cudaGetSymbolAddress((void**)&kl, g_kl);
    cudaGetSymbolAddress((void**)&vh, g_vh);   cudaGetSymbolAddress((void**)&vl, g_vl);
    cudaGetSymbolAddress((void**)&yh, g_yh);   cudaGetSymbolAddress((void**)&yl, g_yl);
    cudaGetSymbolAddress((void**)&wqh, g_wqkvT_hi); cudaGetSymbolAddress((void**)&wql, g_wqkvT_lo);
    cudaGetSymbolAddress((void**)&woh, g_woutT_hi); cudaGetSymbolAddress((void**)&wol, g_woutT_lo);

    cudaFuncSetAttribute(gemm_hmma, cudaFuncAttributeMaxDynamicSharedMemorySize, 3 * GSTG);
    cudaFuncSetAttribute(attn_hmma, cudaFuncAttributeMaxDynamicSharedMemorySize, 2 * 36864);

    // 0) prep: weight transpose+split, x split
    transpose_split<<<dim3((3 * Cc) / 32, Cc / 32), dim3(32, 8)>>>(w_qkv, wqh, wql, Cc, 3 * Cc);
    transpose_split<<<dim3(Cc / 32, Cc / 32), dim3(32, 8)>>>(w_out, woh, wol, Cc, Cc);
    split_x<<<(NTOK * Cc / 4) / 256, 256>>>(x, xh, xl);

    // 1) qkv GEMM -> split head-major Q(scaled)/K/V
    gemm_hmma<<<dim3((3 * Cc) / 128, NTOK / 128), 256, 3 * GSTG>>>(
        xh, xl, wqh, wql, nullptr, qh, ql, kh, kl, vh, vl, NTOK, 3 * Cc, Cc, 0);

    // 2) causal flash attention -> split y
    attn_hmma<<<dim3(Tt / 128, Bb * Hh), 256, 2 * 36864>>>(qh, ql, kh, kl, vh, vl, yh, yl);

    // 3) out = y @ w_out (fp32 out)
    gemm_hmma<<<dim3(Cc / 128, NTOK / 128), 256, 3 * GSTG>>>(
        yh, yl, woh, wol, out, nullptr, nullptr, nullptr, nullptr, nullptr, nullptr,
        NTOK, Cc, Cc, 1);
}

// round 5
// speedup vs baseline: 4.4171x; 1.0214x over previous
#include <cuda_runtime.h>
#include <cuda_bf16.h>
#include <cstdint>

#define Bb 2
#define Tt 4096
#define Cc 768
#define Hh 12
#define Dd 64

#define NTOK   (Bb * Tt)          // 8192
#define RSB    144                // padded smem row stride: 128B data + 16B
#define GSTG   73728              // GEMM stage bytes
#define ASTG   36864              // attn stage bytes
#define SCL    0.18033688011112042f   // (1/sqrt(64)) * log2(e)

// ---------------------------------------------------------------------------
// Scratch (device globals)
// ---------------------------------------------------------------------------
__device__ __nv_bfloat16 g_xh[(size_t)NTOK * Cc], g_xl[(size_t)NTOK * Cc];
__device__ __nv_bfloat16 g_qh[(size_t)Bb * Hh * Tt * Dd], g_ql[(size_t)Bb * Hh * Tt * Dd];
__device__ __nv_bfloat16 g_kh[(size_t)Bb * Hh * Tt * Dd], g_kl[(size_t)Bb * Hh * Tt * Dd];
__device__ __nv_bfloat16 g_vh[(size_t)Bb * Hh * Tt * Dd], g_vl[(size_t)Bb * Hh * Tt * Dd];
__device__ __nv_bfloat16 g_yh[(size_t)NTOK * Cc], g_yl[(size_t)NTOK * Cc];
__device__ __nv_bfloat16 g_wqkvT_hi[(size_t)3 * Cc * Cc], g_wqkvT_lo[(size_t)3 * Cc * Cc];
__device__ __nv_bfloat16 g_woutT_hi[(size_t)Cc * Cc],     g_woutT_lo[(size_t)Cc * Cc];

// ---------------------------------------------------------------------------
// Helpers
// ---------------------------------------------------------------------------
__device__ __forceinline__ uint32_t smem_u32(const void* p) {
    uint32_t a;
    asm("{ .reg .u64 t; cvta.to.shared.u64 t, %1; cvt.u32.u64 %0, t; }" : "=r"(a) : "l"(p));
    return a;
}
__device__ __forceinline__ void ldsm4(uint32_t r[4], uint32_t a) {
    asm volatile("ldmatrix.sync.aligned.m8n8.x4.shared.b16 {%0,%1,%2,%3}, [%4];"
                 : "=r"(r[0]), "=r"(r[1]), "=r"(r[2]), "=r"(r[3]) : "r"(a));
}
__device__ __forceinline__ void ldsm4t(uint32_t r[4], uint32_t a) {
    asm volatile("ldmatrix.sync.aligned.m8n8.x4.trans.shared.b16 {%0,%1,%2,%3}, [%4];"
                 : "=r"(r[0]), "=r"(r[1]), "=r"(r[2]), "=r"(r[3]) : "r"(a));
}
__device__ __forceinline__ void mma16816(float* c, const uint32_t* a, const uint32_t* b) {
    asm volatile("mma.sync.aligned.m16n8k16.row.col.f32.bf16.bf16.f32 "
                 "{%0,%1,%2,%3}, {%4,%5,%6,%7}, {%8,%9}, {%0,%1,%2,%3};"
                 : "+f"(c[0]), "+f"(c[1]), "+f"(c[2]), "+f"(c[3])
                 : "r"(a[0]), "r"(a[1]), "r"(a[2]), "r"(a[3]), "r"(b[0]), "r"(b[1]));
}
__device__ __forceinline__ float ex2(float x) {
    float y; asm("ex2.approx.f32 %0, %1;" : "=f"(y) : "f"(x)); return y;
}
__device__ __forceinline__ uint32_t bfbits(__nv_bfloat162 v) {
    uint32_t u; *(reinterpret_cast<__nv_bfloat162*>(&u)) = v; return u;
}
__device__ __forceinline__ void split2(float a, float b, uint32_t& hi, uint32_t& lo) {
    __nv_bfloat162 h = __floats2bfloat162_rn(a, b);
    __nv_bfloat162 l = __floats2bfloat162_rn(a - __bfloat162float(h.x),
                                             b - __bfloat162float(h.y));
    hi = bfbits(h); lo = bfbits(l);
}
__device__ __forceinline__ void cpa16(uint32_t dst, const void* src) {
    asm volatile("cp.async.cg.shared.global [%0], [%1], 16;" :: "r"(dst), "l"(src));
}
#define CP_COMMIT() asm volatile("cp.async.commit_group;" ::: "memory")
#define CP_WAIT(n)  asm volatile("cp.async.wait_group %0;" :: "n"(n) : "memory")

// ---------------------------------------------------------------------------
// Prep kernels
// ---------------------------------------------------------------------------
__global__ __launch_bounds__(256) void transpose_split(const float* __restrict__ W,
                                                       __nv_bfloat16* __restrict__ Thi,
                                                       __nv_bfloat16* __restrict__ Tlo,
                                                       int K, int N) {
    __shared__ float tile[32][33];
    int n0 = blockIdx.x * 32, k0 = blockIdx.y * 32;
    int tx = threadIdx.x, ty = threadIdx.y;
#pragma unroll
    for (int i = 0; i < 4; i++)
        tile[ty + i * 8][tx] = W[(size_t)(k0 + ty + i * 8) * N + n0 + tx];
    __syncthreads();
#pragma unroll
    for (int i = 0; i < 4; i++) {
        float v = tile[tx][ty + i * 8];
        __nv_bfloat16 h = __float2bfloat16(v);
        __nv_bfloat16 l = __float2bfloat16(v - __bfloat162float(h));
        size_t o = (size_t)(n0 + ty + i * 8) * K + k0 + tx;
        Thi[o] = h; Tlo[o] = l;
    }
}

__global__ __launch_bounds__(256) void split_x(const float* __restrict__ X,
                                               __nv_bfloat16* __restrict__ Xh,
                                               __nv_bfloat16* __restrict__ Xl) {
    int i = blockIdx.x * 256 + threadIdx.x;
    float4 v = ((const float4*)X)[i];
    uint32_t h01, l01, h23, l23;
    split2(v.x, v.y, h01, l01);
    split2(v.z, v.w, h23, l23);
    ((uint2*)Xh)[i] = make_uint2(h01, h23);
    ((uint2*)Xl)[i] = make_uint2(l01, l23);
}

// ---------------------------------------------------------------------------
// HMMA bf16x3 GEMM, pre-split operands, single-sync 3-stage cp.async pipeline.
// Block 128x128, BK=64, 8 warps (32x64 warp tile).
// Stage: Ah 0, Al 18432, Bh 36864, Bl 55296.
// mode 0: qkv epilogue -> split head-major Q(scaled)/K/V.  mode 1: fp32 C.
// ---------------------------------------------------------------------------
__global__ __launch_bounds__(256, 1) void gemm_hmma(
    const __nv_bfloat16* __restrict__ Ah, const __nv_bfloat16* __restrict__ Al,
    const __nv_bfloat16* __restrict__ Wh, const __nv_bfloat16* __restrict__ Wl,
    float* __restrict__ Cout,
    __nv_bfloat16* __restrict__ Qh, __nv_bfloat16* __restrict__ Ql,
    __nv_bfloat16* __restrict__ Kh, __nv_bfloat16* __restrict__ Kl,
    __nv_bfloat16* __restrict__ Vh, __nv_bfloat16* __restrict__ Vl,
    int M, int N, int K, int mode) {
    extern __shared__ __align__(128) char sm[];
    const int tid = threadIdx.x, lane = tid & 31, wid = tid >> 5;
    const int wm = (wid & 3) * 32, wn = (wid >> 2) * 64;
    const int crow = blockIdx.y * 128, ccol = blockIdx.x * 128;
    const uint32_t sb = smem_u32(sm);
    const int nch = K / 64;

    float acc[2][8][4];
#pragma unroll
    for (int i = 0; i < 2; i++)
#pragma unroll
        for (int j = 0; j < 8; j++)
#pragma unroll
            for (int e = 0; e < 4; e++) acc[i][j][e] = 0.f;

    auto STAGE = [&](int c, int s) {
        uint32_t sbuf = sb + (uint32_t)s * GSTG;
        const __nv_bfloat16* a0 = Ah + (size_t)crow * K + c * 64;
        const __nv_bfloat16* a1 = Al + (size_t)crow * K + c * 64;
        const __nv_bfloat16* b0 = Wh + (size_t)ccol * K + c * 64;
        const __nv_bfloat16* b1 = Wl + (size_t)ccol * K + c * 64;
#pragma unroll
        for (int i = 0; i < 4; i++) {
            int idx = tid + i * 256, r = idx >> 3, ch = idx & 7;
            size_t go = (size_t)r * K + ch * 8;
            uint32_t so = (uint32_t)(r * RSB + ch * 16);
            cpa16(sbuf + so,          a0 + go);
            cpa16(sbuf + 18432 + so,  a1 + go);
            cpa16(sbuf + 36864 + so,  b0 + go);
            cpa16(sbuf + 55296 + so,  b1 + go);
        }
    };
    auto MMAC = [&](int s) {
        const uint32_t sA = sb + (uint32_t)s * GSTG;
        const uint32_t sB = sA + 36864;
#pragma unroll
        for (int ks = 0; ks < 4; ks++) {
            uint32_t ah[2][4], al[2][4];
#pragma unroll
            for (int mt = 0; mt < 2; mt++) {
                uint32_t ad = sA + (uint32_t)((wm + mt * 16 + (lane & 15)) * RSB +
                                              ks * 32 + ((lane & 16) ? 16 : 0));
                ldsm4(ah[mt], ad);
                ldsm4(al[mt], ad + 18432);
            }
#pragma unroll
            for (int q = 0; q < 4; q++) {
                uint32_t bd = sB + (uint32_t)((wn + q * 16 + (lane & 7) + ((lane >> 4) << 3)) * RSB +
                                              ks * 32 + ((lane & 8) ? 16 : 0));
                uint32_t bh[4], bl[4];
                ldsm4(bh, bd);
                ldsm4(bl, bd + 18432);
#pragma unroll
                for (int mt = 0; mt < 2; mt++) {
                    mma16816(acc[mt][2 * q],     ah[mt], bh);
                    mma16816(acc[mt][2 * q],     al[mt], bh);
                    mma16816(acc[mt][2 * q],     ah[mt], bl);
                    mma16816(acc[mt][2 * q + 1], ah[mt], bh + 2);
                    mma16816(acc[mt][2 * q + 1], al[mt], bh + 2);
                    mma16816(acc[mt][2 * q + 1], ah[mt], bl + 2);
                }
            }
        }
    };

    STAGE(0, 0); CP_COMMIT();
    STAGE(1, 1); CP_COMMIT();
    for (int c = 0; c < nch; c++) {
        CP_WAIT(1);
        __syncthreads();                 // stage c ready; everyone done with (c-1)%3
        if (c + 2 < nch) STAGE(c + 2, (c + 2) % 3);
        CP_COMMIT();
        MMAC(c % 3);
    }

    if (mode == 1) {
#pragma unroll
        for (int mt = 0; mt < 2; mt++)
#pragma unroll
            for (int nt = 0; nt < 8; nt++) {
                int row = crow + wm + mt * 16 + (lane >> 2);
                int col = ccol + wn + nt * 8 + (lane & 3) * 2;
                *(float2*)(Cout + (size_t)row * N + col) =
                    make_float2(acc[mt][nt][0], acc[mt][nt][1]);
                *(float2*)(Cout + (size_t)(row + 8) * N + col) =
                    make_float2(acc[mt][nt][2], acc[mt][nt][3]);
            }
    } else {
        __nv_bfloat16* PH[3] = {Qh, Kh, Vh};
        __nv_bfloat16* PL[3] = {Ql, Kl, Vl};
        const int selb = ccol / Cc;
        const float scale = (selb == 0) ? SCL : 1.f;
        __nv_bfloat16* ph = PH[selb];
        __nv_bfloat16* pl = PL[selb];
#pragma unroll
        for (int mt = 0; mt < 2; mt++)
#pragma unroll
            for (int nt = 0; nt < 8; nt++) {
                int row = crow + wm + mt * 16 + (lane >> 2);
                int col = ccol + wn + nt * 8 + (lane & 3) * 2;
                int rem = col - selb * Cc, h = rem >> 6, d = rem & 63;
#pragma unroll
                for (int half = 0; half < 2; half++) {
                    int r2 = row + half * 8;
                    int b = r2 >> 12, t = r2 & 4095;
                    size_t off = ((size_t)(b * Hh + h) * Tt + t) * Dd + d;
                    uint32_t hi, lo;
                    split2(acc[mt][nt][2 * half] * scale,
                           acc[mt][nt][2 * half + 1] * scale, hi, lo);
                    *(uint32_t*)(ph + off) = hi;
                    *(uint32_t*)(pl + off) = lo;
                }
            }
    }
}

// ---------------------------------------------------------------------------
// HMMA causal flash attention. 128 query rows/CTA (8 warps x 16), 64-key tiles,
// pre-split bf16 operands, single-sync 3-stage cp.async staging.
// Stage: Kh 0, Kl 9216, Vh 18432, Vl 27648 (36864 B) x3.
// ---------------------------------------------------------------------------
__global__ __launch_bounds__(256, 1) void attn_hmma(
    const __nv_bfloat16* __restrict__ Qh_, const __nv_bfloat16* __restrict__ Ql_,
    const __nv_bfloat16* __restrict__ Kh_, const __nv_bfloat16* __restrict__ Kl_,
    const __nv_bfloat16* __restrict__ Vh_, const __nv_bfloat16* __restrict__ Vl_,
    __nv_bfloat16* __restrict__ Yh, __nv_bfloat16* __restrict__ Yl) {
    extern __shared__ __align__(128) char sm[];
    const int tid = threadIdx.x, lane = tid & 31, wid = tid >> 5;
    const int bh = blockIdx.y, b = bh / Hh, h = bh % Hh;
    const int qt = (int)gridDim.x - 1 - (int)blockIdx.x;   // big tiles first
    const int q0 = qt * 128;
    const int m0 = wid * 16;
    const uint32_t sb = smem_u32(sm);
    const size_t hb = (size_t)bh * Tt;

    // ---- stage Q (pre-scaled, pre-split) into buf0 area, load fragments ----
    {
        const __nv_bfloat16* qg0 = Qh_ + (hb + q0) * Dd;
        const __nv_bfloat16* qg1 = Ql_ + (hb + q0) * Dd;
#pragma unroll
        for (int i = 0; i < 4; i++) {
            int idx = tid + i * 256, r = idx >> 3, ch = idx & 7;
            *(uint4*)(sm + r * RSB + ch * 16)         = *(const uint4*)(qg0 + r * Dd + ch * 8);
            *(uint4*)(sm + 18432 + r * RSB + ch * 16) = *(const uint4*)(qg1 + r * Dd + ch * 8);
        }
    }
    __syncthreads();
    uint32_t qh[4][4], ql[4][4];
#pragma unroll
    for (int ks = 0; ks < 4; ks++) {
        uint32_t ad = sb + (uint32_t)((m0 + (lane & 15)) * RSB + ks * 32 + ((lane & 16) ? 16 : 0));
        ldsm4(qh[ks], ad);
        ldsm4(ql[ks], ad + 18432);
    }
    __syncthreads();

    auto STAGEKV = [&](int kt, int s) {
        uint32_t sbuf = sb + (uint32_t)s * ASTG;
        const __nv_bfloat16* k0 = Kh_ + (hb + kt * 64) * Dd;
        const __nv_bfloat16* k1 = Kl_ + (hb + kt * 64) * Dd;
        const __nv_bfloat16* v0 = Vh_ + (hb + kt * 64) * Dd;
        const __nv_bfloat16* v1 = Vl_ + (hb + kt * 64) * Dd;
#pragma unroll
        for (int i = 0; i < 2; i++) {
            int idx = tid + i * 256, r = idx >> 3, ch = idx & 7;
            size_t go = (size_t)r * Dd + ch * 8;
            uint32_t so = (uint32_t)(r * RSB + ch * 16);
            cpa16(sbuf + so,          k0 + go);
            cpa16(sbuf + 9216 + so,   k1 + go);
            cpa16(sbuf + 18432 + so,  v0 + go);
            cpa16(sbuf + 27648 + so,  v1 + go);
        }
    };

    float o[8][4];
#pragma unroll
    for (int j = 0; j < 8; j++)
#pragma unroll
        for (int e = 0; e < 4; e++) o[j][e] = 0.f;
    float m1 = -1e30f, m2 = -1e30f, l1 = 0.f, l2 = 0.f;
    const int nkt = 2 * qt + 2;

    STAGEKV(0, 0); CP_COMMIT();
    STAGEKV(1, 1); CP_COMMIT();

    for (int kt = 0; kt < nkt; kt++) {
        CP_WAIT(1);
        __syncthreads();                 // stage kt ready; kt-1's reads done
        if (kt + 2 < nkt) STAGEKV(kt + 2, (kt + 2) % 3);
        CP_COMMIT();
        const uint32_t sbuf = sb + (uint32_t)(kt % 3) * ASTG;

        if (kt * 64 > q0 + m0 + 15) continue;   // warp tile fully masked

        // ---- S = Q @ K^T (bf16x3) ----
        float cS[8][4];
#pragma unroll
        for (int j = 0; j < 8; j++)
#pragma unroll
            for (int e = 0; e < 4; e++) cS[j][e] = 0.f;
#pragma unroll
        for (int ks = 0; ks < 4; ks++) {
#pragma unroll
            for (int q2 = 0; q2 < 4; q2++) {
                uint32_t bd = sbuf + (uint32_t)((q2 * 16 + (lane & 7) + ((lane >> 4) << 3)) * RSB +
                                                ks * 32 + ((lane & 8) ? 16 : 0));
                uint32_t kh4[4], kl4[4];
                ldsm4(kh4, bd);
                ldsm4(kl4, bd + 9216);
                mma16816(cS[2 * q2],     qh[ks], kh4);
                mma16816(cS[2 * q2],     ql[ks], kh4);
                mma16816(cS[2 * q2],     qh[ks], kl4);
                mma16816(cS[2 * q2 + 1], qh[ks], kh4 + 2);
                mma16816(cS[2 * q2 + 1], ql[ks], kh4 + 2);
                mma16816(cS[2 * q2 + 1], qh[ks], kl4 + 2);
            }
        }

        // ---- causal mask ----
        if (kt >= 2 * qt) {
            int r1 = q0 + m0 + (lane >> 2);
#pragma unroll
            for (int nt = 0; nt < 8; nt++) {
                int k0c = kt * 64 + nt * 8 + (lane & 3) * 2;
                if (k0c     > r1)     cS[nt][0] = -1e30f;
                if (k0c + 1 > r1)     cS[nt][1] = -1e30f;
                if (k0c     > r1 + 8) cS[nt][2] = -1e30f;
                if (k0c + 1 > r1 + 8) cS[nt][3] = -1e30f;
            }
        }

        // ---- online softmax ----
        float mx1 = -1e30f, mx2 = -1e30f;
#pragma unroll
        for (int nt = 0; nt < 8; nt++) {
            mx1 = fmaxf(mx1, fmaxf(cS[nt][0], cS[nt][1]));
            mx2 = fmaxf(mx2, fmaxf(cS[nt][2], cS[nt][3]));
        }
        mx1 = fmaxf(mx1, __shfl_xor_sync(0xffffffffu, mx1, 1));
        mx1 = fmaxf(mx1, __shfl_xor_sync(0xffffffffu, mx1, 2));
        mx2 = fmaxf(mx2, __shfl_xor_sync(0xffffffffu, mx2, 1));
        mx2 = fmaxf(mx2, __shfl_xor_sync(0xffffffffu, mx2, 2));
        float mn1 = fmaxf(m1, mx1), mn2 = fmaxf(m2, mx2);
        float a1 = ex2(m1 - mn1), a2 = ex2(m2 - mn2);
        float s1 = 0.f, s2 = 0.f;
        uint32_t ph[8], pl[8], ph8[8], pl8[8];
#pragma unroll
        for (int nt = 0; nt < 8; nt++) {
            float p0 = ex2(cS[nt][0] - mn1), p1 = ex2(cS[nt][1] - mn1);
            float p2 = ex2(cS[nt][2] - mn2), p3 = ex2(cS[nt][3] - mn2);
            s1 += p0 + p1;
            s2 += p2 + p3;
            split2(p0, p1, ph[nt], pl[nt]);
            split2(p2, p3, ph8[nt], pl8[nt]);
        }
        s1 += __shfl_xor_sync(0xffffffffu, s1, 1);
        s1 += __shfl_xor_sync(0xffffffffu, s1, 2);
        s2 += __shfl_xor_sync(0xffffffffu, s2, 1);
        s2 += __shfl_xor_sync(0xffffffffu, s2, 2);
        l1 = l1 * a1 + s1;
        l2 = l2 * a2 + s2;
#pragma unroll
        for (int nt = 0; nt < 8; nt++) {
            o[nt][0] *= a1; o[nt][1] *= a1;
            o[nt][2] *= a2; o[nt][3] *= a2;
        }
        m1 = mn1;
        m2 = mn2;

        // ---- O += P @ V (bf16x3) ----
#pragma unroll
        for (int kk = 0; kk < 4; kk++) {
            uint32_t ah4[4] = {ph[2 * kk], ph8[2 * kk], ph[2 * kk + 1], ph8[2 * kk + 1]};
            uint32_t al4[4] = {pl[2 * kk], pl8[2 * kk], pl[2 * kk + 1], pl8[2 * kk + 1]};
#pragma unroll
            for (int q2 = 0; q2 < 4; q2++) {
                uint32_t vd = sbuf + 18432u + (uint32_t)((kk * 16 + (lane & 15)) * RSB +
                                                         (q2 * 16 + ((lane & 16) ? 8 : 0)) * 2);
                uint32_t vh4[4], vl4[4];
                ldsm4t(vh4, vd);
                ldsm4t(vl4, vd + 9216);
                mma16816(o[2 * q2],     ah4, vh4);
                mma16816(o[2 * q2],     al4, vh4);
                mma16816(o[2 * q2],     ah4, vl4);
                mma16816(o[2 * q2 + 1], ah4, vh4 + 2);
                mma16816(o[2 * q2 + 1], al4, vh4 + 2);
                mma16816(o[2 * q2 + 1], ah4, vl4 + 2);
            }
        }
    }

    // ---- epilogue: O /= l, split, store y (token-major) ----
    float i1 = 1.f / l1, i2 = 1.f / l2;
    int row = q0 + m0 + (lane >> 2);
#pragma unroll
    for (int nt = 0; nt < 8; nt++) {
        int col = h * Dd + nt * 8 + (lane & 3) * 2;
        size_t off1 = ((size_t)b * Tt + row) * Cc + col;
        size_t off2 = off1 + (size_t)8 * Cc;
        uint32_t hi, lo;
        split2(o[nt][0] * i1, o[nt][1] * i1, hi, lo);
        *(uint32_t*)(Yh + off1) = hi;
        *(uint32_t*)(Yl + off1) = lo;
        split2(o[nt][2] * i2, o[nt][3] * i2, hi, lo);
        *(uint32_t*)(Yh + off2) = hi;
        *(uint32_t*)(Yl + off2) = lo;
    }
}

// ---------------------------------------------------------------------------
extern "C" void kernel_launch(void* const* d_in, const int* in_sizes, int n_in,
                              void* d_out, int out_size) {
    const float* x     = (const float*)d_in[0];
    const float* w_qkv = (const float*)d_in[1];
    const float* w_out = (const float*)d_in[2];
    float* out = (float*)d_out;

    __nv_bfloat16 *xh, *xl, *qh, *ql, *kh, *kl, *vh, *vl, *yh, *yl;
    __nv_bfloat16 *wqh, *wql, *woh, *wol;
    cudaGetSymbolAddress((void**)&xh, g_xh);   cudaGetSymbolAddress((void**)&xl, g_xl);
    cudaGetSymbolAddress((void**)&qh, g_qh);   cudaGetSymbolAddress((void**)&ql, g_ql);
    cudaGetSymbolAddress((void**)&kh, g_kh);   cudaGetSymbolAddress((void**)&kl, g_kl);
    cudaGetSymbolAddress((void**)&vh, g_vh);   cudaGetSymbolAddress((void**)&vl, g_vl);
    cudaGetSymbolAddress((void**)&yh, g_yh);   cudaGetSymbolAddress((void**)&yl, g_yl);
    cudaGetSymbolAddress((void**)&wqh, g_wqkvT_hi); cudaGetSymbolAddress((void**)&wql, g_wqkvT_lo);
    cudaGetSymbolAddress((void**)&woh, g_woutT_hi); cudaGetSymbolAddress((void**)&wol, g_woutT_lo);

    cudaFuncSetAttribute(gemm_hmma, cudaFuncAttributeMaxDynamicSharedMemorySize, 3 * GSTG);
    cudaFuncSetAttribute(attn_hmma, cudaFuncAttributeMaxDynamicSharedMemorySize, 3 * ASTG);

    // 0) prep
    transpose_split<<<dim3((3 * Cc) / 32, Cc / 32), dim3(32, 8)>>>(w_qkv, wqh, wql, Cc, 3 * Cc);
    transpose_split<<<dim3(Cc / 32, Cc / 32), dim3(32, 8)>>>(w_out, woh, wol, Cc, Cc);
    split_x<<<(NTOK * Cc / 4) / 256, 256>>>(x, xh, xl);

    // 1) qkv GEMM -> split head-major Q(scaled)/K/V
    gemm_hmma<<<dim3((3 * Cc) / 128, NTOK / 128), 256, 3 * GSTG>>>(
        xh, xl, wqh, wql, nullptr, qh, ql, kh, kl, vh, vl, NTOK, 3 * Cc, Cc, 0);

    // 2) causal flash attention -> split y
    attn_hmma<<<dim3(Tt / 128, Bb * Hh), 256, 3 * ASTG>>>(qh, ql, kh, kl, vh, vl, yh, yl);

    // 3) out = y @ w_out (fp32 out)
    gemm_hmma<<<dim3(Cc / 128, NTOK / 128), 256, 3 * GSTG>>>(
        yh, yl, woh, wol, out, nullptr, nullptr, nullptr, nullptr, nullptr, nullptr,
        NTOK, Cc, Cc, 1);
}